// round 14
// baseline (speedup 1.0000x reference)
#include <cuda_runtime.h>
#include <cuda_bf16.h>

// AnisotropicDistance:
// out[b,i,j] = alpha_i * max(||p_i-p_j||^2 + along^2*(||t_i||^2 - 2), 0) + beta_i * along^2
// along = (p_i.t_i) - (p_j.t_i)
//
// R13: R12 kernel (9 FMA2/pair, no epilogue, clamp dropped — normal_sq >= 0 by
// Cauchy-Schwarz, fp-rounding only vs 1e-3 gate; PDL overlap) with one change:
// __launch_bounds__(256,5) caps regs at 51 -> 5 CTAs/SM (~55% occ) for deeper
// store MLP against the DRAM write ceiling.

#define MAX_PTS 32768  // B*N max supported (actual: 2*8192 = 16384)

typedef unsigned long long ull;

// j-side SoA:
__device__ float g_px[MAX_PTS];
__device__ float g_py[MAX_PTS];
__device__ float g_pz[MAX_PTS];
// i-side constants, duplicated (v,v) into b64, packed 2 per ulonglong2:
// slot 0: (ntx, nty)      slot 1: (ntz, pds)
// slot 2: (alnpx, alnpy)  slot 3: (alnpz, g)     g = al*c1 + be
// slot 4: (al, alsqi)
__device__ ulonglong2 g2c[MAX_PTS * 5];

#define FMA2(d, a, b, c) asm("fma.rn.f32x2 %0, %1, %2, %3;" : "=l"(d) : "l"(a), "l"(b), "l"(c))
#define MUL2(d, a, b)    asm("mul.rn.f32x2 %0, %1, %2;"     : "=l"(d) : "l"(a), "l"(b))
#define PACK2(d, lo, hi) asm("mov.b64 %0, {%1, %2};"        : "=l"(d) : "f"(lo), "f"(hi))

__device__ __forceinline__ ull dup_f(float v) {
    ull d; PACK2(d, v, v); return d;
}

__global__ void precompute_kernel(const float* __restrict__ points,
                                  const float* __restrict__ pdir,
                                  const float* __restrict__ lin,
                                  int total) {
    int idx = blockIdx.x * blockDim.x + threadIdx.x;
    if (idx >= total) return;
    float px = points[idx * 3 + 0];
    float py = points[idx * 3 + 1];
    float pz = points[idx * 3 + 2];
    float tx = pdir[idx * 3 + 0];
    float ty = pdir[idx * 3 + 1];
    float tz = pdir[idx * 3 + 2];
    float l  = lin[idx];

    g_px[idx] = px; g_py[idx] = py; g_pz[idx] = pz;
    float sq = fmaf(px, px, fmaf(py, py, pz * pz));

    float al = 2.0f * (1.0f + l);
    float be = 0.5f * (1.0f - l);
    float c1 = fmaf(tx, tx, fmaf(ty, ty, tz * tz)) - 2.0f;
    float g  = fmaf(al, c1, be);          // al*c1 + be

    ulonglong2 c;
    c.x = dup_f(-tx);             c.y = dup_f(-ty);
    g2c[idx * 5 + 0] = c;
    c.x = dup_f(-tz);             c.y = dup_f(fmaf(px, tx, fmaf(py, ty, pz * tz)));
    g2c[idx * 5 + 1] = c;
    c.x = dup_f(al * -2.0f * px); c.y = dup_f(al * -2.0f * py);
    g2c[idx * 5 + 2] = c;
    c.x = dup_f(al * -2.0f * pz); c.y = dup_f(g);
    g2c[idx * 5 + 3] = c;
    c.x = dup_f(al);              c.y = dup_f(al * sq);
    g2c[idx * 5 + 4] = c;
}

#define TI 16          // i-rows per block
#define TPB 256        // threads per block
#define JV 4           // j per thread (one 16B store) -> block covers 1024 j

// One packed pair (2 j-elements) -> packed result in 'res' (no epilogue):
// res = al*(sqi - 2 pj.pi + sqj) + g*along^2
#define PAIR_COMPUTE(pjx, pjy, pjz, sqj, res)                          \
    {                                                                  \
        ull u, a2;                                                     \
        FMA2(u, pjz, ntz, pds);                                        \
        FMA2(u, pjy, nty, u);                                          \
        FMA2(u, pjx, ntx, u);            /* along */                   \
        MUL2(a2, u, u);                  /* along^2 */                 \
        FMA2(res, pjz, alnpz, alsqi);                                  \
        FMA2(res, pjy, alnpy, res);                                    \
        FMA2(res, pjx, alnpx, res);      /* al*(sqi - 2 pj.pi) */      \
        FMA2(res, al, sqj, res);         /* + al*sqj */                \
        FMA2(res, a2, gg, res);          /* + (al*c1+be)*a2 */         \
    }

__global__ __launch_bounds__(TPB, 5) void aniso_main_kernel(float* __restrict__ out, int N) {
    __shared__ ulonglong2 s_c[TI * 5];

    // PDL: wait until precompute_kernel's global writes are visible.
    cudaGridDependencySynchronize();

    const int b  = blockIdx.z;
    const int i0 = blockIdx.y * TI;
    const int j4 = blockIdx.x * TPB + threadIdx.x;   // float4 index in j
    const int j  = j4 * JV;
    const int base = b * N;

    if (threadIdx.x < TI * 5) {
        s_c[threadIdx.x] = g2c[(base + i0) * 5 + threadIdx.x];
    }
    __syncthreads();

    if (j >= N) return;

    // j-side loads (coalesced float4, L2-resident), packed into b64 pairs once
    const float4 pjx = reinterpret_cast<const float4*>(g_px + base)[j4];
    const float4 pjy = reinterpret_cast<const float4*>(g_py + base)[j4];
    const float4 pjz = reinterpret_cast<const float4*>(g_pz + base)[j4];

    ull ax01, ax23, ay01, ay23, az01, az23;
    PACK2(ax01, pjx.x, pjx.y); PACK2(ax23, pjx.z, pjx.w);
    PACK2(ay01, pjy.x, pjy.y); PACK2(ay23, pjy.z, pjy.w);
    PACK2(az01, pjz.x, pjz.y); PACK2(az23, pjz.z, pjz.w);

    // sqj computed in-registers (loop-invariant), packed f32x2
    ull as01, as23;
    {
        ull t;
        MUL2(t, az01, az01); FMA2(t, ay01, ay01, t); FMA2(as01, ax01, ax01, t);
        MUL2(t, az23, az23); FMA2(t, ay23, ay23, t); FMA2(as23, ax23, ax23, t);
    }

    float* orow = out + ((size_t)b * N + i0) * N + j;

    #pragma unroll
    for (int ii = 0; ii < TI; ii++) {
        const ulonglong2 c0 = s_c[ii * 5 + 0];
        const ulonglong2 c1v = s_c[ii * 5 + 1];
        const ulonglong2 c2 = s_c[ii * 5 + 2];
        const ulonglong2 c3 = s_c[ii * 5 + 3];
        const ulonglong2 c4 = s_c[ii * 5 + 4];
        const ull ntx = c0.x, nty = c0.y, ntz = c1v.x, pds = c1v.y;
        const ull alnpx = c2.x, alnpy = c2.y, alnpz = c3.x, gg = c3.y;
        const ull al = c4.x, alsqi = c4.y;

        ulonglong2 o;
        PAIR_COMPUTE(ax01, ay01, az01, as01, o.x);
        PAIR_COMPUTE(ax23, ay23, az23, as23, o.y);

        __stcs(reinterpret_cast<ulonglong2*>(orow), o);   // 16B streaming store
        orow += N;
    }
}

extern "C" void kernel_launch(void* const* d_in, const int* in_sizes, int n_in,
                              void* d_out, int out_size) {
    const float* points = (const float*)d_in[0];
    const float* pdir   = (const float*)d_in[1];
    const float* lin    = (const float*)d_in[2];
    float* out = (float*)d_out;

    const int total = in_sizes[0] / 3;                 // B*N points
    const int N = (int)((long long)out_size / total);  // out = B*N*N
    const int B = total / N;

    precompute_kernel<<<(total + 255) / 256, 256>>>(points, pdir, lin, total);

    // Main kernel with PDL: launch overlaps precompute execution.
    dim3 grid((N + TPB * JV - 1) / (TPB * JV), (N + TI - 1) / TI, B);

    cudaLaunchConfig_t cfg = {};
    cfg.gridDim = grid;
    cfg.blockDim = dim3(TPB, 1, 1);
    cfg.dynamicSmemBytes = 0;
    cfg.stream = 0;
    cudaLaunchAttribute attrs[1];
    attrs[0].id = cudaLaunchAttributeProgrammaticStreamSerialization;
    attrs[0].val.programmaticStreamSerializationAllowed = 1;
    cfg.attrs = attrs;
    cfg.numAttrs = 1;
    cudaLaunchKernelEx(&cfg, aniso_main_kernel, out, N);
}